// round 13
// baseline (speedup 1.0000x reference)
#include <cuda_runtime.h>
#include <math.h>

#define B_    16
#define T_    128
#define V_    32000
#define H_    768
#define P_    384
#define NBOW_ 64
#define BT_   (B_ * T_)
#define EPS_  0.05f
#define TAU_  0.07f
#define CSH_  16.0f

#define NSIDE 48
#define NBLK  (NSIDE + BT_)

// ---- scratch (__device__ globals; no allocation allowed) ----
__device__ float g_ce[BT_];
__device__ float g_vf[BT_];
__device__ float g_z [2 * B_ * P_];
__device__ float g_gram[B_ * B_];
__device__ float g_bce [B_];
__device__ unsigned int g_done = 0;

// forced-order vector loads (volatile asm keeps batches grouped -> real MLP)
__device__ __forceinline__ float4 ldg4(const float4* p) {
    float4 v;
    asm volatile("ld.global.v4.f32 {%0,%1,%2,%3},[%4];"
                 : "=f"(v.x), "=f"(v.y), "=f"(v.z), "=f"(v.w) : "l"(p));
    return v;
}
__device__ __forceinline__ float4 ldg4cs(const float4* p) {   // streaming (evict-first)
    float4 v;
    asm volatile("ld.global.cs.v4.f32 {%0,%1,%2,%3},[%4];"
                 : "=f"(v.x), "=f"(v.y), "=f"(v.z), "=f"(v.w) : "l"(p));
    return v;
}

// ---- 384-thread block sum ----
__device__ __forceinline__ float blockreduce384(float v, float* red, int tid) {
    red[tid] = v;
    __syncthreads();
    if (tid < 128) red[tid] += red[tid + 256];
    __syncthreads();
    for (int off = 128; off > 0; off >>= 1) {
        if (tid < off) red[tid] += red[tid + off];
        __syncthreads();
    }
    float r = red[0];
    __syncthreads();
    return r;
}

// ============================================================
// k_mega: grid = NBLK, block = 384, min 4 blocks/SM.
// ============================================================
__global__ __launch_bounds__(384, 4) void k_mega(
        const float* __restrict__ logits, const int* __restrict__ labels,
        const float* __restrict__ enc,
        const float* __restrict__ dec, const int* __restrict__ mask,
        const float* __restrict__ Wb, const float* __restrict__ bb,
        const float* __restrict__ g_e, const float* __restrict__ be_,
        const float* __restrict__ W1e, const float* __restrict__ b1e,
        const float* __restrict__ W2e, const float* __restrict__ b2e,
        const float* __restrict__ g_t, const float* __restrict__ bt_,
        const float* __restrict__ W1t, const float* __restrict__ b1t,
        const float* __restrict__ W2t, const float* __restrict__ b2t,
        float* __restrict__ out) {
    const int bid = blockIdx.x;
    const int tid = threadIdx.x;

    __shared__ float shs[384], sht[384];
    __shared__ __align__(16) float px[H_];
    __shared__ __align__(16) float ln[H_];
    __shared__ __align__(16) float h1s[P_];
    __shared__ __align__(16) float spart[1536];
    __shared__ float red[P_];
    __shared__ float mk[T_];
    __shared__ __align__(16) float er_s[H_];
    __shared__ float gpart[384];
    __shared__ float term[NBOW_];
    __shared__ int   bow_hit[NBOW_];
    __shared__ float acc_terms[6];
    __shared__ int   s_last;

    if (bid >= NSIDE) {
        // ================= CE token (depth-2 software pipeline) =================
        const int tok = bid - NSIDE;
        const float4* p = reinterpret_cast<const float4*>(logits + (size_t)tok * V_) + tid;

        float s0 = 0.f, s1 = 0.f;
        float t0 = 0.f, t1 = 0.f;

        // 20 full quads per thread = 10 stages of 2, pipelined
        float4 c0 = ldg4cs(p);
        float4 c1 = ldg4cs(p + 384);
        #pragma unroll
        for (int gi = 0; gi < 10; gi++) {
            float4 n0, n1;
            if (gi < 9) {
                n0 = ldg4cs(p + (2 * gi + 2) * 384);
                n1 = ldg4cs(p + (2 * gi + 3) * 384);
            }
            t0 += c0.x; t1 += c0.y; t0 += c0.z; t1 += c0.w;
            s0 += __expf(c0.x - CSH_);
            s1 += __expf(c0.y - CSH_);
            s0 += __expf(c0.z - CSH_);
            s1 += __expf(c0.w - CSH_);
            t0 += c1.x; t1 += c1.y; t0 += c1.z; t1 += c1.w;
            s0 += __expf(c1.x - CSH_);
            s1 += __expf(c1.y - CSH_);
            s0 += __expf(c1.z - CSH_);
            s1 += __expf(c1.w - CSH_);
            c0 = n0; c1 = n1;
        }
        // tail: 320 quads at offset 7680
        if (tid < 320) {
            float4 v = ldg4cs(p - tid + 7680 + tid);
            t0 += v.x; t1 += v.y; t0 += v.z; t1 += v.w;
            s0 += __expf(v.x - CSH_);
            s1 += __expf(v.y - CSH_);
            s0 += __expf(v.z - CSH_);
            s1 += __expf(v.w - CSH_);
        }
        float S  = s0 + s1;
        float TS = t0 + t1;

        shs[tid] = S; sht[tid] = TS;
        __syncthreads();
        if (tid < 128) { shs[tid] += shs[tid + 256]; sht[tid] += sht[tid + 256]; }
        __syncthreads();
        for (int off = 128; off > 0; off >>= 1) {
            if (tid < off) { shs[tid] += shs[tid + off]; sht[tid] += sht[tid + off]; }
            __syncthreads();
        }

        if (tid == 0) {
            float lse = CSH_ + logf(shs[0]);
            int lab = labels[tok];
            bool valid = (lab != 0) && (lab != -100);
            int lc = lab < 0 ? 0 : (lab >= V_ ? V_ - 1 : lab);
            float xl = logits[(size_t)tok * V_ + lc];
            float lp_lab = xl - lse;
            float lp_sum = sht[0] - (float)V_ * lse;
            float loss = -((1.0f - EPS_) * lp_lab + (EPS_ / (float)V_) * lp_sum);
            g_ce[tok] = valid ? loss : 0.0f;
            g_vf[tok] = valid ? 1.0f : 0.0f;
        }
    } else if (bid < 2 * B_) {
        // ================= projection row =================
        const bool is_e = bid < B_;
        const int row  = is_e ? bid : bid - B_;
        const float* g  = is_e ? g_e : g_t;
        const float* bn = is_e ? be_ : bt_;
        const float* W1 = is_e ? W1e : W1t;
        const float* b1 = is_e ? b1e : b1t;
        const float* W2 = is_e ? W2e : W2t;
        const float* b2 = is_e ? b2e : b2t;
        float* z = g_z + bid * P_;

        if (is_e) {
            px[tid]      = enc[row * H_ + tid];
            px[tid + P_] = enc[row * H_ + tid + P_];
            __syncthreads();
        } else {
            if (tid < T_) mk[tid] = (float)mask[row * T_ + tid];
            __syncthreads();
            if (tid < 128) red[tid] = mk[tid];
            __syncthreads();
            if (tid < 64) red[tid] += red[tid + 64];
            __syncthreads();
            if (tid < 32) {
                float v = red[tid] + red[tid + 32];
                #pragma unroll
                for (int off = 16; off > 0; off >>= 1) v += __shfl_down_sync(0xffffffffu, v, off);
                if (tid == 0) red[0] = 1.0f / fmaxf(v, 1.0f);
            }
            __syncthreads();
            float minv = red[0];

            const int jq = tid % 192, c = tid / 192;
            const float4* d4 = reinterpret_cast<const float4*>(dec);
            const size_t base = (size_t)(row * T_ + c * 64) * (H_ / 4) + jq;
            float4 acc = make_float4(0.f, 0.f, 0.f, 0.f);
            for (int t = 0; t < 64; t += 8) {
                float4 vb[8];
                #pragma unroll
                for (int u = 0; u < 8; u++) vb[u] = ldg4(d4 + base + (size_t)(t + u) * (H_ / 4));
                #pragma unroll
                for (int u = 0; u < 8; u++) {
                    float m = mk[c * 64 + t + u];
                    acc.x = fmaf(vb[u].x, m, acc.x);
                    acc.y = fmaf(vb[u].y, m, acc.y);
                    acc.z = fmaf(vb[u].z, m, acc.z);
                    acc.w = fmaf(vb[u].w, m, acc.w);
                }
            }
            reinterpret_cast<float4*>(spart)[c * 192 + jq] = acc;
            __syncthreads();
            #pragma unroll
            for (int r = 0; r < 2; r++) {
                int j = tid + r * P_;
                px[j] = (spart[j] + spart[768 + j]) * minv;
            }
            __syncthreads();
        }

        float a0 = px[tid], a1 = px[tid + P_];
        float mean = blockreduce384(a0 + a1, red, tid) * (1.0f / (float)H_);
        float d0 = a0 - mean, d1 = a1 - mean;
        float var = blockreduce384(d0 * d0 + d1 * d1, red, tid) * (1.0f / (float)H_);
        float inv = rsqrtf(var + 1e-5f);
        ln[tid]      = d0 * inv * g[tid]      + bn[tid];
        ln[tid + P_] = d1 * inv * g[tid + P_] + bn[tid + P_];
        __syncthreads();

        {
            const int jq = tid % 96, c = tid / 96;
            const int k0 = c * 192;
            const float4* w4 = reinterpret_cast<const float4*>(W1);
            float4 acc = make_float4(0.f, 0.f, 0.f, 0.f);
            for (int kk = 0; kk < 192; kk += 8) {
                float4 vb[8];
                #pragma unroll
                for (int u = 0; u < 8; u++) vb[u] = ldg4(w4 + (size_t)(k0 + kk + u) * 96 + jq);
                #pragma unroll
                for (int u = 0; u < 8; u++) {
                    float s = ln[k0 + kk + u];
                    acc.x = fmaf(s, vb[u].x, acc.x);
                    acc.y = fmaf(s, vb[u].y, acc.y);
                    acc.z = fmaf(s, vb[u].z, acc.z);
                    acc.w = fmaf(s, vb[u].w, acc.w);
                }
            }
            reinterpret_cast<float4*>(spart)[c * 96 + jq] = acc;
        }
        __syncthreads();
        {
            float h1 = b1[tid] + spart[tid] + spart[384 + tid] + spart[768 + tid] + spart[1152 + tid];
            h1s[tid] = 0.5f * h1 * (1.0f + erff(h1 * 0.70710678118654752f));
        }
        __syncthreads();

        float acc2;
        {
            const int jq = tid % 96, c = tid / 96;
            const int k0 = c * 96;
            const float4* w4 = reinterpret_cast<const float4*>(W2);
            float4 acc = make_float4(0.f, 0.f, 0.f, 0.f);
            for (int kk = 0; kk < 96; kk += 8) {
                float4 vb[8];
                #pragma unroll
                for (int u = 0; u < 8; u++) vb[u] = ldg4(w4 + (size_t)(k0 + kk + u) * 96 + jq);
                #pragma unroll
                for (int u = 0; u < 8; u++) {
                    float s = h1s[k0 + kk + u];
                    acc.x = fmaf(s, vb[u].x, acc.x);
                    acc.y = fmaf(s, vb[u].y, acc.y);
                    acc.z = fmaf(s, vb[u].z, acc.z);
                    acc.w = fmaf(s, vb[u].w, acc.w);
                }
            }
            reinterpret_cast<float4*>(spart)[c * 96 + jq] = acc;
        }
        __syncthreads();
        acc2 = b2[tid] + spart[tid] + spart[384 + tid] + spart[768 + tid] + spart[1152 + tid];

        float n2 = blockreduce384(acc2 * acc2, red, tid);
        float nrm = fmaxf(sqrtf(n2), 1e-12f);
        z[tid] = acc2 / nrm;
    } else {
        // ================= gram + BoW row =================
        const int b = bid - 2 * B_;

        er_s[tid]      = enc[b * H_ + tid];
        er_s[tid + P_] = enc[b * H_ + tid + P_];
        if (tid < NBOW_) bow_hit[tid] = 0;
        __syncthreads();

        if (tid < T_) {
            int lab = labels[b * T_ + tid];
            bool valid = (lab != 0) && (lab != -100);
            int lc = lab < 0 ? 0 : (lab >= V_ ? V_ - 1 : lab);
            if (valid && (lc % 500 == 0)) {
                int q = lc / 500;
                if (q < NBOW_) bow_hit[q] = 1;
            }
        }

        {
            const int j = tid / 24, c = tid % 24;
            const float4* e4 = reinterpret_cast<const float4*>(enc);
            const size_t base = (size_t)(j * H_ + c * 32) / 4;
            float4 vb[8];
            #pragma unroll
            for (int u = 0; u < 8; u++) vb[u] = ldg4(e4 + base + u);
            float acc = 0.0f;
            #pragma unroll
            for (int u = 0; u < 8; u++) {
                const float* av = er_s + c * 32 + u * 4;
                acc = fmaf(av[0], vb[u].x, acc);
                acc = fmaf(av[1], vb[u].y, acc);
                acc = fmaf(av[2], vb[u].z, acc);
                acc = fmaf(av[3], vb[u].w, acc);
            }
            gpart[j * 24 + c] = acc;
        }

        {
            const int i16 = tid & 15, c24 = tid >> 4;
            const float4* w4 = reinterpret_cast<const float4*>(Wb);
            const int k0 = c24 * 32;
            float4 acc = make_float4(0.f, 0.f, 0.f, 0.f);
            for (int kk = 0; kk < 32; kk += 8) {
                float4 vb[8];
                #pragma unroll
                for (int u = 0; u < 8; u++) vb[u] = ldg4(w4 + (size_t)(k0 + kk + u) * 16 + i16);
                #pragma unroll
                for (int u = 0; u < 8; u++) {
                    float e = er_s[k0 + kk + u];
                    acc.x = fmaf(e, vb[u].x, acc.x);
                    acc.y = fmaf(e, vb[u].y, acc.y);
                    acc.z = fmaf(e, vb[u].z, acc.z);
                    acc.w = fmaf(e, vb[u].w, acc.w);
                }
            }
            reinterpret_cast<float4*>(spart)[c24 * 16 + i16] = acc;
        }
        __syncthreads();

        if (tid < 16) {
            float s = 0.f;
            #pragma unroll
            for (int c = 0; c < 24; c++) s += gpart[tid * 24 + c];
            g_gram[b * 16 + tid] = s;
        } else if (tid >= 64 && tid < 128) {
            int i = tid - 64;
            float bl = bb[i];
            #pragma unroll
            for (int c = 0; c < 24; c++) bl += spart[c * 64 + i];
            float tt = (float)bow_hit[i];
            term[i] = fmaxf(bl, 0.0f) - bl * tt + log1pf(expf(-fabsf(bl)));
        }
        __syncthreads();
        if (tid < 32) {
            float v = term[tid] + term[tid + 32];
            #pragma unroll
            for (int off = 16; off > 0; off >>= 1) v += __shfl_down_sync(0xffffffffu, v, off);
            if (tid == 0) g_bce[b] = v;
        }
    }

    // ================= last-block finisher =================
    __threadfence();
    __syncthreads();
    if (tid == 0) s_last = (atomicAdd(&g_done, 1u) == (unsigned)(NBLK - 1));
    __syncthreads();
    if (!s_last) return;

    float a = 0.f, w = 0.f;
    for (int i = tid; i < BT_; i += 384) { a += g_ce[i]; w += g_vf[i]; }
    float ce_num = blockreduce384(a, red, tid);
    float ce_den = blockreduce384(w, red, tid);

    if (tid < 256) {
        int i = tid >> 4, j = tid & 15;
        const float4* ze = reinterpret_cast<const float4*>(g_z + i * P_);
        const float4* zt = reinterpret_cast<const float4*>(g_z + (B_ + j) * P_);
        float acc = 0.f;
        #pragma unroll 8
        for (int k = 0; k < 96; k++) {
            float4 x = ze[k], y = zt[k];
            acc = fmaf(x.x, y.x, acc);
            acc = fmaf(x.y, y.y, acc);
            acc = fmaf(x.z, y.z, acc);
            acc = fmaf(x.w, y.w, acc);
        }
        gpart[tid] = acc / TAU_;
    }
    __syncthreads();

    if (tid < B_) {
        float mx = -1e30f, mc = -1e30f;
        #pragma unroll
        for (int j = 0; j < B_; j++) { mx = fmaxf(mx, gpart[tid * 16 + j]); mc = fmaxf(mc, gpart[j * 16 + tid]); }
        float se = 0.f, sc = 0.f;
        #pragma unroll
        for (int j = 0; j < B_; j++) { se += expf(gpart[tid * 16 + j] - mx); sc += expf(gpart[j * 16 + tid] - mc); }
        term[tid]      = -(gpart[tid * 16 + tid] - (mx + logf(se)));
        term[32 + tid] = -(gpart[tid * 16 + tid] - (mc + logf(sc)));
    }
    __syncthreads();
    if (tid == 0) {
        float li = 0.f, lj = 0.f;
        #pragma unroll
        for (int i = 0; i < B_; i++) { li += term[i]; lj += term[32 + i]; }
        acc_terms[2] = 0.5f * (li + lj) / (float)B_;
        float bs = 0.f;
        #pragma unroll
        for (int i = 0; i < B_; i++) bs += g_bce[i];
        acc_terms[3] = bs / (float)(B_ * NBOW_);
    }

    float dacc = 0.f;
    if (tid < 256) {
        int i = tid >> 4, j = tid & 15;
        if (i != j) {
            float ni = fmaxf(sqrtf(g_gram[i * 16 + i]), 1e-12f);
            float nj = fmaxf(sqrtf(g_gram[j * 16 + j]), 1e-12f);
            dacc = fabsf(g_gram[i * 16 + j] / (ni * nj));
        }
    }
    float dsum = blockreduce384(dacc, red, tid);

    float vacc = 0.f;
    for (int c = tid; c < H_; c += 384) {
        float mu = 0.f;
        #pragma unroll
        for (int b = 0; b < B_; b++) mu += enc[b * H_ + c];
        mu *= (1.0f / (float)B_);
        float ss = 0.f;
        #pragma unroll
        for (int b = 0; b < B_; b++) { float d = enc[b * H_ + c] - mu; ss += d * d; }
        vacc += expf(-(ss * (1.0f / (float)(B_ - 1))));
    }
    float vsum = blockreduce384(vacc, red, tid);

    if (tid == 0) {
        float ce = ce_num / fmaxf(ce_den, 1.0f);
        out[0] = 1.0f * ce + 0.5f * acc_terms[2] + 0.2f * acc_terms[3]
               + 0.1f * (dsum / (float)(B_ * B_ - B_)) + 0.05f * (vsum / (float)H_);
        g_done = 0;
    }
}

// ============================================================
extern "C" void kernel_launch(void* const* d_in, const int* in_sizes, int n_in,
                              void* d_out, int out_size) {
    const float* logits = (const float*)d_in[0];
    const int*   labels = (const int*)  d_in[1];
    const int*   amask  = (const int*)  d_in[2];
    const float* enc    = (const float*)d_in[3];
    const float* dec    = (const float*)d_in[4];
    const float* ln_g_e = (const float*)d_in[5];
    const float* ln_b_e = (const float*)d_in[6];
    const float* W1e    = (const float*)d_in[7];
    const float* b1e    = (const float*)d_in[8];
    const float* W2e    = (const float*)d_in[9];
    const float* b2e    = (const float*)d_in[10];
    const float* ln_g_t = (const float*)d_in[11];
    const float* ln_b_t = (const float*)d_in[12];
    const float* W1t    = (const float*)d_in[13];
    const float* b1t    = (const float*)d_in[14];
    const float* W2t    = (const float*)d_in[15];
    const float* b2t    = (const float*)d_in[16];
    const float* Wb     = (const float*)d_in[17];
    const float* bb     = (const float*)d_in[18];
    float* out = (float*)d_out;

    k_mega<<<NBLK, 384>>>(logits, labels, enc, dec, amask, Wb, bb,
                          ln_g_e, ln_b_e, W1e, b1e, W2e, b2e,
                          ln_g_t, ln_b_t, W1t, b1t, W2t, b2t, out);
}

// round 14
// speedup vs baseline: 1.0277x; 1.0277x over previous
#include <cuda_runtime.h>
#include <math.h>

#define B_    16
#define T_    128
#define V_    32000
#define H_    768
#define P_    384
#define NBOW_ 64
#define BT_   (B_ * T_)
#define EPS_  0.05f
#define TAU_  0.07f
#define CSH_  16.0f

#define NSIDE 48
#define NCE   512          // CE blocks; each handles 4 tokens
#define TPB   4            // tokens per CE block (NCE*TPB == BT_)
#define NBLK  (NSIDE + NCE)

// ---- scratch (__device__ globals; no allocation allowed) ----
__device__ float g_ce[BT_];
__device__ float g_vf[BT_];
__device__ float g_z [2 * B_ * P_];
__device__ float g_gram[B_ * B_];
__device__ float g_bce [B_];
__device__ unsigned int g_done = 0;

// forced-order vector loads (volatile asm keeps batches grouped -> real MLP)
__device__ __forceinline__ float4 ldg4(const float4* p) {
    float4 v;
    asm volatile("ld.global.v4.f32 {%0,%1,%2,%3},[%4];"
                 : "=f"(v.x), "=f"(v.y), "=f"(v.z), "=f"(v.w) : "l"(p));
    return v;
}
__device__ __forceinline__ float4 ldg4cs(const float4* p) {   // streaming (evict-first)
    float4 v;
    asm volatile("ld.global.cs.v4.f32 {%0,%1,%2,%3},[%4];"
                 : "=f"(v.x), "=f"(v.y), "=f"(v.z), "=f"(v.w) : "l"(p));
    return v;
}

// ---- 384-thread block sum ----
__device__ __forceinline__ float blockreduce384(float v, float* red, int tid) {
    red[tid] = v;
    __syncthreads();
    if (tid < 128) red[tid] += red[tid + 256];
    __syncthreads();
    for (int off = 128; off > 0; off >>= 1) {
        if (tid < off) red[tid] += red[tid + off];
        __syncthreads();
    }
    float r = red[0];
    __syncthreads();
    return r;
}

// ============================================================
// k_mega: grid = NBLK (560 = one balanced wave), block = 384.
// ============================================================
__global__ __launch_bounds__(384, 4) void k_mega(
        const float* __restrict__ logits, const int* __restrict__ labels,
        const float* __restrict__ enc,
        const float* __restrict__ dec, const int* __restrict__ mask,
        const float* __restrict__ Wb, const float* __restrict__ bb,
        const float* __restrict__ g_e, const float* __restrict__ be_,
        const float* __restrict__ W1e, const float* __restrict__ b1e,
        const float* __restrict__ W2e, const float* __restrict__ b2e,
        const float* __restrict__ g_t, const float* __restrict__ bt_,
        const float* __restrict__ W1t, const float* __restrict__ b1t,
        const float* __restrict__ W2t, const float* __restrict__ b2t,
        float* __restrict__ out) {
    const int bid = blockIdx.x;
    const int tid = threadIdx.x;

    __shared__ float shs[384], sht[384];
    __shared__ __align__(16) float px[H_];
    __shared__ __align__(16) float ln[H_];
    __shared__ __align__(16) float h1s[P_];
    __shared__ __align__(16) float spart[1536];
    __shared__ float red[P_];
    __shared__ float mk[T_];
    __shared__ __align__(16) float er_s[H_];
    __shared__ float gpart[384];
    __shared__ float term[NBOW_];
    __shared__ int   bow_hit[NBOW_];
    __shared__ float acc_terms[6];
    __shared__ int   s_last;

    if (bid >= NSIDE) {
        // ================= CE: 4 tokens per block =================
        #pragma unroll 1
        for (int tt = 0; tt < TPB; tt++) {
            const int tok = (bid - NSIDE) * TPB + tt;
            const float4* p = reinterpret_cast<const float4*>(logits + (size_t)tok * V_);

            float s0 = 0.f, s1 = 0.f, s2 = 0.f, s3 = 0.f;
            float t0 = 0.f, t1 = 0.f, t2 = 0.f, t3 = 0.f;
            // 8000 quads = 384*20 + 320 ; 20 iters as 5 forced batches of 4
            #pragma unroll
            for (int gi = 0; gi < 5; gi++) {
                float4 vb[4];
                #pragma unroll
                for (int u = 0; u < 4; u++) vb[u] = ldg4cs(p + tid + (gi * 4 + u) * 384);
                #pragma unroll
                for (int u = 0; u < 4; u++) {
                    t0 += vb[u].x; t1 += vb[u].y; t2 += vb[u].z; t3 += vb[u].w;
                    s0 += __expf(vb[u].x - CSH_);
                    s1 += __expf(vb[u].y - CSH_);
                    s2 += __expf(vb[u].z - CSH_);
                    s3 += __expf(vb[u].w - CSH_);
                }
            }
            if (tid < 320) {
                float4 v = ldg4cs(p + 7680 + tid);
                t0 += v.x; t1 += v.y; t2 += v.z; t3 += v.w;
                s0 += __expf(v.x - CSH_);
                s1 += __expf(v.y - CSH_);
                s2 += __expf(v.z - CSH_);
                s3 += __expf(v.w - CSH_);
            }
            float S  = (s0 + s1) + (s2 + s3);
            float TS = (t0 + t1) + (t2 + t3);

            shs[tid] = S; sht[tid] = TS;
            __syncthreads();
            if (tid < 128) { shs[tid] += shs[tid + 256]; sht[tid] += sht[tid + 256]; }
            __syncthreads();
            for (int off = 128; off > 0; off >>= 1) {
                if (tid < off) { shs[tid] += shs[tid + off]; sht[tid] += sht[tid + off]; }
                __syncthreads();
            }

            if (tid == 0) {
                float lse = CSH_ + logf(shs[0]);
                int lab = labels[tok];
                bool valid = (lab != 0) && (lab != -100);
                int lc = lab < 0 ? 0 : (lab >= V_ ? V_ - 1 : lab);
                float xl = logits[(size_t)tok * V_ + lc];
                float lp_lab = xl - lse;
                float lp_sum = sht[0] - (float)V_ * lse;
                float loss = -((1.0f - EPS_) * lp_lab + (EPS_ / (float)V_) * lp_sum);
                g_ce[tok] = valid ? loss : 0.0f;
                g_vf[tok] = valid ? 1.0f : 0.0f;
            }
            __syncthreads();
        }
    } else if (bid < 2 * B_) {
        // ================= projection row =================
        const bool is_e = bid < B_;
        const int row  = is_e ? bid : bid - B_;
        const float* g  = is_e ? g_e : g_t;
        const float* bn = is_e ? be_ : bt_;
        const float* W1 = is_e ? W1e : W1t;
        const float* b1 = is_e ? b1e : b1t;
        const float* W2 = is_e ? W2e : W2t;
        const float* b2 = is_e ? b2e : b2t;
        float* z = g_z + bid * P_;

        if (is_e) {
            px[tid]      = enc[row * H_ + tid];
            px[tid + P_] = enc[row * H_ + tid + P_];
            __syncthreads();
        } else {
            if (tid < T_) mk[tid] = (float)mask[row * T_ + tid];
            __syncthreads();
            if (tid < 128) red[tid] = mk[tid];
            __syncthreads();
            if (tid < 64) red[tid] += red[tid + 64];
            __syncthreads();
            if (tid < 32) {
                float v = red[tid] + red[tid + 32];
                #pragma unroll
                for (int off = 16; off > 0; off >>= 1) v += __shfl_down_sync(0xffffffffu, v, off);
                if (tid == 0) red[0] = 1.0f / fmaxf(v, 1.0f);
            }
            __syncthreads();
            float minv = red[0];

            const int jq = tid % 192, c = tid / 192;
            const float4* d4 = reinterpret_cast<const float4*>(dec);
            const size_t base = (size_t)(row * T_ + c * 64) * (H_ / 4) + jq;
            float4 acc = make_float4(0.f, 0.f, 0.f, 0.f);
            for (int t = 0; t < 64; t += 8) {
                float4 vb[8];
                #pragma unroll
                for (int u = 0; u < 8; u++) vb[u] = ldg4(d4 + base + (size_t)(t + u) * (H_ / 4));
                #pragma unroll
                for (int u = 0; u < 8; u++) {
                    float m = mk[c * 64 + t + u];
                    acc.x = fmaf(vb[u].x, m, acc.x);
                    acc.y = fmaf(vb[u].y, m, acc.y);
                    acc.z = fmaf(vb[u].z, m, acc.z);
                    acc.w = fmaf(vb[u].w, m, acc.w);
                }
            }
            reinterpret_cast<float4*>(spart)[c * 192 + jq] = acc;
            __syncthreads();
            #pragma unroll
            for (int r = 0; r < 2; r++) {
                int j = tid + r * P_;
                px[j] = (spart[j] + spart[768 + j]) * minv;
            }
            __syncthreads();
        }

        float a0 = px[tid], a1 = px[tid + P_];
        float mean = blockreduce384(a0 + a1, red, tid) * (1.0f / (float)H_);
        float d0 = a0 - mean, d1 = a1 - mean;
        float var = blockreduce384(d0 * d0 + d1 * d1, red, tid) * (1.0f / (float)H_);
        float inv = rsqrtf(var + 1e-5f);
        ln[tid]      = d0 * inv * g[tid]      + bn[tid];
        ln[tid + P_] = d1 * inv * g[tid + P_] + bn[tid + P_];
        __syncthreads();

        {
            const int jq = tid % 96, c = tid / 96;
            const int k0 = c * 192;
            const float4* w4 = reinterpret_cast<const float4*>(W1);
            float4 acc = make_float4(0.f, 0.f, 0.f, 0.f);
            for (int kk = 0; kk < 192; kk += 8) {
                float4 vb[8];
                #pragma unroll
                for (int u = 0; u < 8; u++) vb[u] = ldg4(w4 + (size_t)(k0 + kk + u) * 96 + jq);
                #pragma unroll
                for (int u = 0; u < 8; u++) {
                    float s = ln[k0 + kk + u];
                    acc.x = fmaf(s, vb[u].x, acc.x);
                    acc.y = fmaf(s, vb[u].y, acc.y);
                    acc.z = fmaf(s, vb[u].z, acc.z);
                    acc.w = fmaf(s, vb[u].w, acc.w);
                }
            }
            reinterpret_cast<float4*>(spart)[c * 96 + jq] = acc;
        }
        __syncthreads();
        {
            float h1 = b1[tid] + spart[tid] + spart[384 + tid] + spart[768 + tid] + spart[1152 + tid];
            h1s[tid] = 0.5f * h1 * (1.0f + erff(h1 * 0.70710678118654752f));
        }
        __syncthreads();

        float acc2;
        {
            const int jq = tid % 96, c = tid / 96;
            const int k0 = c * 96;
            const float4* w4 = reinterpret_cast<const float4*>(W2);
            float4 acc = make_float4(0.f, 0.f, 0.f, 0.f);
            for (int kk = 0; kk < 96; kk += 8) {
                float4 vb[8];
                #pragma unroll
                for (int u = 0; u < 8; u++) vb[u] = ldg4(w4 + (size_t)(k0 + kk + u) * 96 + jq);
                #pragma unroll
                for (int u = 0; u < 8; u++) {
                    float s = h1s[k0 + kk + u];
                    acc.x = fmaf(s, vb[u].x, acc.x);
                    acc.y = fmaf(s, vb[u].y, acc.y);
                    acc.z = fmaf(s, vb[u].z, acc.z);
                    acc.w = fmaf(s, vb[u].w, acc.w);
                }
            }
            reinterpret_cast<float4*>(spart)[c * 96 + jq] = acc;
        }
        __syncthreads();
        acc2 = b2[tid] + spart[tid] + spart[384 + tid] + spart[768 + tid] + spart[1152 + tid];

        float n2 = blockreduce384(acc2 * acc2, red, tid);
        float nrm = fmaxf(sqrtf(n2), 1e-12f);
        z[tid] = acc2 / nrm;
    } else {
        // ================= gram + BoW row =================
        const int b = bid - 2 * B_;

        er_s[tid]      = enc[b * H_ + tid];
        er_s[tid + P_] = enc[b * H_ + tid + P_];
        if (tid < NBOW_) bow_hit[tid] = 0;
        __syncthreads();

        if (tid < T_) {
            int lab = labels[b * T_ + tid];
            bool valid = (lab != 0) && (lab != -100);
            int lc = lab < 0 ? 0 : (lab >= V_ ? V_ - 1 : lab);
            if (valid && (lc % 500 == 0)) {
                int q = lc / 500;
                if (q < NBOW_) bow_hit[q] = 1;
            }
        }

        {
            const int j = tid / 24, c = tid % 24;
            const float4* e4 = reinterpret_cast<const float4*>(enc);
            const size_t base = (size_t)(j * H_ + c * 32) / 4;
            float4 vb[8];
            #pragma unroll
            for (int u = 0; u < 8; u++) vb[u] = ldg4(e4 + base + u);
            float acc = 0.0f;
            #pragma unroll
            for (int u = 0; u < 8; u++) {
                const float* av = er_s + c * 32 + u * 4;
                acc = fmaf(av[0], vb[u].x, acc);
                acc = fmaf(av[1], vb[u].y, acc);
                acc = fmaf(av[2], vb[u].z, acc);
                acc = fmaf(av[3], vb[u].w, acc);
            }
            gpart[j * 24 + c] = acc;
        }

        {
            const int i16 = tid & 15, c24 = tid >> 4;
            const float4* w4 = reinterpret_cast<const float4*>(Wb);
            const int k0 = c24 * 32;
            float4 acc = make_float4(0.f, 0.f, 0.f, 0.f);
            for (int kk = 0; kk < 32; kk += 8) {
                float4 vb[8];
                #pragma unroll
                for (int u = 0; u < 8; u++) vb[u] = ldg4(w4 + (size_t)(k0 + kk + u) * 16 + i16);
                #pragma unroll
                for (int u = 0; u < 8; u++) {
                    float e = er_s[k0 + kk + u];
                    acc.x = fmaf(e, vb[u].x, acc.x);
                    acc.y = fmaf(e, vb[u].y, acc.y);
                    acc.z = fmaf(e, vb[u].z, acc.z);
                    acc.w = fmaf(e, vb[u].w, acc.w);
                }
            }
            reinterpret_cast<float4*>(spart)[c24 * 16 + i16] = acc;
        }
        __syncthreads();

        if (tid < 16) {
            float s = 0.f;
            #pragma unroll
            for (int c = 0; c < 24; c++) s += gpart[tid * 24 + c];
            g_gram[b * 16 + tid] = s;
        } else if (tid >= 64 && tid < 128) {
            int i = tid - 64;
            float bl = bb[i];
            #pragma unroll
            for (int c = 0; c < 24; c++) bl += spart[c * 64 + i];
            float tt = (float)bow_hit[i];
            term[i] = fmaxf(bl, 0.0f) - bl * tt + log1pf(expf(-fabsf(bl)));
        }
        __syncthreads();
        if (tid < 32) {
            float v = term[tid] + term[tid + 32];
            #pragma unroll
            for (int off = 16; off > 0; off >>= 1) v += __shfl_down_sync(0xffffffffu, v, off);
            if (tid == 0) g_bce[b] = v;
        }
    }

    // ================= last-block finisher =================
    __threadfence();
    __syncthreads();
    if (tid == 0) s_last = (atomicAdd(&g_done, 1u) == (unsigned)(NBLK - 1));
    __syncthreads();
    if (!s_last) return;

    float a = 0.f, w = 0.f;
    for (int i = tid; i < BT_; i += 384) { a += g_ce[i]; w += g_vf[i]; }
    float ce_num = blockreduce384(a, red, tid);
    float ce_den = blockreduce384(w, red, tid);

    if (tid < 256) {
        int i = tid >> 4, j = tid & 15;
        const float4* ze = reinterpret_cast<const float4*>(g_z + i * P_);
        const float4* zt = reinterpret_cast<const float4*>(g_z + (B_ + j) * P_);
        float acc = 0.f;
        #pragma unroll 8
        for (int k = 0; k < 96; k++) {
            float4 x = ze[k], y = zt[k];
            acc = fmaf(x.x, y.x, acc);
            acc = fmaf(x.y, y.y, acc);
            acc = fmaf(x.z, y.z, acc);
            acc = fmaf(x.w, y.w, acc);
        }
        gpart[tid] = acc / TAU_;
    }
    __syncthreads();

    if (tid < B_) {
        float mx = -1e30f, mc = -1e30f;
        #pragma unroll
        for (int j = 0; j < B_; j++) { mx = fmaxf(mx, gpart[tid * 16 + j]); mc = fmaxf(mc, gpart[j * 16 + tid]); }
        float se = 0.f, sc = 0.f;
        #pragma unroll
        for (int j = 0; j < B_; j++) { se += expf(gpart[tid * 16 + j] - mx); sc += expf(gpart[j * 16 + tid] - mc); }
        term[tid]      = -(gpart[tid * 16 + tid] - (mx + logf(se)));
        term[32 + tid] = -(gpart[tid * 16 + tid] - (mc + logf(sc)));
    }
    __syncthreads();
    if (tid == 0) {
        float li = 0.f, lj = 0.f;
        #pragma unroll
        for (int i = 0; i < B_; i++) { li += term[i]; lj += term[32 + i]; }
        acc_terms[2] = 0.5f * (li + lj) / (float)B_;
        float bs = 0.f;
        #pragma unroll
        for (int i = 0; i < B_; i++) bs += g_bce[i];
        acc_terms[3] = bs / (float)(B_ * NBOW_);
    }

    float dacc = 0.f;
    if (tid < 256) {
        int i = tid >> 4, j = tid & 15;
        if (i != j) {
            float ni = fmaxf(sqrtf(g_gram[i * 16 + i]), 1e-12f);
            float nj = fmaxf(sqrtf(g_gram[j * 16 + j]), 1e-12f);
            dacc = fabsf(g_gram[i * 16 + j] / (ni * nj));
        }
    }
    float dsum = blockreduce384(dacc, red, tid);

    float vacc = 0.f;
    for (int c = tid; c < H_; c += 384) {
        float mu = 0.f;
        #pragma unroll
        for (int b = 0; b < B_; b++) mu += enc[b * H_ + c];
        mu *= (1.0f / (float)B_);
        float ss = 0.f;
        #pragma unroll
        for (int b = 0; b < B_; b++) { float d = enc[b * H_ + c] - mu; ss += d * d; }
        vacc += expf(-(ss * (1.0f / (float)(B_ - 1))));
    }
    float vsum = blockreduce384(vacc, red, tid);

    if (tid == 0) {
        float ce = ce_num / fmaxf(ce_den, 1.0f);
        out[0] = 1.0f * ce + 0.5f * acc_terms[2] + 0.2f * acc_terms[3]
               + 0.1f * (dsum / (float)(B_ * B_ - B_)) + 0.05f * (vsum / (float)H_);
        g_done = 0;
    }
}

// ============================================================
extern "C" void kernel_launch(void* const* d_in, const int* in_sizes, int n_in,
                              void* d_out, int out_size) {
    const float* logits = (const float*)d_in[0];
    const int*   labels = (const int*)  d_in[1];
    const int*   amask  = (const int*)  d_in[2];
    const float* enc    = (const float*)d_in[3];
    const float* dec    = (const float*)d_in[4];
    const float* ln_g_e = (const float*)d_in[5];
    const float* ln_b_e = (const float*)d_in[6];
    const float* W1e    = (const float*)d_in[7];
    const float* b1e    = (const float*)d_in[8];
    const float* W2e    = (const float*)d_in[9];
    const float* b2e    = (const float*)d_in[10];
    const float* ln_g_t = (const float*)d_in[11];
    const float* ln_b_t = (const float*)d_in[12];
    const float* W1t    = (const float*)d_in[13];
    const float* b1t    = (const float*)d_in[14];
    const float* W2t    = (const float*)d_in[15];
    const float* b2t    = (const float*)d_in[16];
    const float* Wb     = (const float*)d_in[17];
    const float* bb     = (const float*)d_in[18];
    float* out = (float*)d_out;

    k_mega<<<NBLK, 384>>>(logits, labels, enc, dec, amask, Wb, bb,
                          ln_g_e, ln_b_e, W1e, b1e, W2e, b2e,
                          ln_g_t, ln_b_t, W1t, b1t, W2t, b2t, out);
}